// round 14
// baseline (speedup 1.0000x reference)
#include <cuda_runtime.h>
#include <cstdint>

// Fixed shapes: pred/target = [4, 8192, 3] fp32
#define NB        4
#define NPTS      8192
#define THREADS   128
#define OCC       8
#define IPT       8                    // pred points per lane
#define JT        64                   // targets per tile
#define TILES     (NPTS / JT)          // 128 tiles per combo
#define NCOMBO    (NB * 8)             // 32 (b, ich) combos
#define GRID      (148 * OCC)          // 1184 CTAs: one wave, 37 CTAs/combo
#define INF_BITS  0x7f800000

// Static device scratch.
__device__ float4       g_ppk[NB * NPTS];   // packed pred: (x,y,z,h)
__device__ float4       g_qpk[NB * NPTS];   // packed tgt:  (x,y,z,h)
__device__ int          g_rmin[NB * NPTS];  // int-ordered fp mins (>=0)
__device__ int          g_cmin[NB * NPTS];
__device__ unsigned int g_next[NCOMBO];
__device__ unsigned int g_done;

__device__ __forceinline__ void cp_async16(uint32_t s, const void* g) {
    asm volatile("cp.async.cg.shared.global [%0], [%1], 16;" :: "r"(s), "l"(g) : "memory");
}
__device__ __forceinline__ void cp_commit() {
    asm volatile("cp.async.commit_group;" ::: "memory");
}
__device__ __forceinline__ void cp_wait1() {
    asm volatile("cp.async.wait_group 1;" ::: "memory");
}

// Pack points and reset mins/queues.  32768 threads.
__global__ void chamfer_init_kernel(const float* __restrict__ pred,
                                    const float* __restrict__ tgt) {
    int idx = blockIdx.x * blockDim.x + threadIdx.x;   // 0 .. NB*NPTS-1
    float x = pred[3 * idx], y = pred[3 * idx + 1], z = pred[3 * idx + 2];
    g_ppk[idx] = make_float4(x, y, z, 0.5f * fmaf(x, x, fmaf(y, y, z * z)));
    x = tgt[3 * idx]; y = tgt[3 * idx + 1]; z = tgt[3 * idx + 2];
    g_qpk[idx] = make_float4(x, y, z, 0.5f * fmaf(x, x, fmaf(y, y, z * z)));
    g_rmin[idx] = INF_BITS;
    g_cmin[idx] = INF_BITS;
    if (idx < NCOMBO) g_next[idx] = 0u;
    if (idx == 0) g_done = 0u;
}

// Persistent symmetric cross kernel (R12 math, cp.async-pipelined staging).
//   s = h_q - p.q  (3 FFMA, negated-p source modifiers, q.w = +h_q)
//   rows: min(s) (+h_p at flush);  cols: t = h_p + s, 8-tree, systolic SHFL.
__global__ void __launch_bounds__(THREADS, OCC)
chamfer_cross_kernel(float* __restrict__ out) {
    // Two tile buffers, each duplicated-halves layout:
    //   sq[pc][h][m] = q-tile element h*32 + (m & 31),  m in [0, 64)
    __shared__ float4       sq[2][2][64];
    __shared__ float        scol[4][JT];
    __shared__ unsigned int s_draw;
    __shared__ float        s_red[THREADS];

    const int combo = blockIdx.x & (NCOMBO - 1);
    const int b     = combo >> 3;
    const int ich   = combo & 7;
    const int tid   = threadIdx.x;
    const int w     = tid >> 5;
    const int lane  = tid & 31;

    const float4* Qp = &g_qpk[b * NPTS];
    int* grow = &g_rmin[b * NPTS];
    int* gcol = &g_cmin[b * NPTS];

    // Staging map: tid -> (half, slot); slot 63 idles.
    const int sh = tid >> 6;            // 0/1
    const int sm = tid & 63;            // 0..63
    const int sj = (sh << 5) + (sm & 31);  // tile-local j this thread stages

    // Register-resident pred points (fixed for whole kernel).
    const int ib = ich * 1024 + w * 256 + lane * IPT;
    const float4* Pp = &g_ppk[b * NPTS + ib];
    float px[IPT], py[IPT], pz[IPT], hp[IPT], smin[IPT];
#pragma unroll
    for (int k = 0; k < IPT; k++) {
        float4 p = Pp[k];
        px[k] = p.x; py[k] = p.y; pz[k] = p.z; hp[k] = p.w;
        smin[k] = __int_as_float(INF_BITS);
    }

    uint32_t sq_base[2];
    sq_base[0] = (uint32_t)__cvta_generic_to_shared(&sq[0][0][0]);
    sq_base[1] = (uint32_t)__cvta_generic_to_shared(&sq[1][0][0]);

    // ---- Pipeline prologue: draw t0, t1, t2; stage t0 -> buf0, t1 -> buf1.
    if (tid == 0) s_draw = atomicAdd(&g_next[combo], 1u);
    __syncthreads();
    unsigned int cur = s_draw;
    if (cur < TILES && sm < 63)
        cp_async16(sq_base[0] + (sh * 64 + sm) * 16, &Qp[cur * JT + sj]);
    cp_commit();
    if (tid == 0) s_draw = atomicAdd(&g_next[combo], 1u);
    __syncthreads();
    unsigned int nxt = s_draw;
    if (nxt < TILES && sm < 63)
        cp_async16(sq_base[1] + (sh * 64 + sm) * 16, &Qp[nxt * JT + sj]);
    cp_commit();
    if (tid == 0) s_draw = atomicAdd(&g_next[combo], 1u);
    cp_wait1();                          // t0's group done
    __syncthreads();

    int pc = 0;
    while (cur < TILES) {
        // ---- 64 systolic steps on buf pc; cm rides one SHFL per step.
#pragma unroll
        for (int h = 0; h < 2; h++) {
            const float4* qp = &sq[pc][h][lane];
            float cm = __int_as_float(INF_BITS);
#pragma unroll 8
            for (int n = 0; n < 32; n++) {
                float4 q = qp[n];                    // LDS.128, ptr bump only
                float tm;
#pragma unroll
                for (int k = 0; k < IPT; k += 2) {
                    float s0 = fmaf(-pz[k],     q.z, fmaf(-py[k],     q.y, fmaf(-px[k],     q.x, q.w)));
                    float s1 = fmaf(-pz[k + 1], q.z, fmaf(-py[k + 1], q.y, fmaf(-px[k + 1], q.x, q.w)));
                    smin[k]     = fminf(smin[k],     s0);
                    smin[k + 1] = fminf(smin[k + 1], s1);
                    float t0 = fmaf(s0, 1.0f, hp[k]);    // t = hp + s (FFMA-imm)
                    float t1 = fmaf(s1, 1.0f, hp[k + 1]);
                    float tp = fminf(t0, t1);
                    tm = (k == 0) ? tp : fminf(tm, tp);
                }
                cm = fminf(cm, tm);
                cm = __shfl_sync(0xffffffffu, cm, lane + 1);
            }
            scol[w][h * 32 + lane] = cm;
        }
        __syncthreads();                 // scol complete; buf pc free; s_draw visible

        // Col combine -> global atomic min (2 warps).
        if (tid < JT) {
            float m = fminf(fminf(scol[0][tid], scol[1][tid]),
                            fminf(scol[2][tid], scol[3][tid]));
            atomicMin(&gcol[cur * JT + tid], __float_as_int(m));
        }

        // Stage tile-after-next into the freed buffer; draw 3-ahead.
        unsigned int nn = s_draw;
        if (nn < TILES && sm < 63)
            cp_async16(sq_base[pc] + (sh * 64 + sm) * 16, &Qp[nn * JT + sj]);
        cp_commit();
        if (tid == 0) s_draw = atomicAdd(&g_next[combo], 1u);
        cp_wait1();                      // nxt's group done
        __syncthreads();                 // combine done before scol overwrite; buf visible

        cur = nxt; nxt = nn; pc ^= 1;
    }

    // Row flush once per CTA (add hp back here).
#pragma unroll
    for (int k = 0; k < IPT; k++)
        atomicMin(&grow[ib + k], __float_as_int(hp[k] + smin[k]));

    // Last CTA reduces everything to the scalar output.
    __threadfence();
    __shared__ int s_last;
    if (tid == 0) s_last = (atomicAdd(&g_done, 1u) == GRID - 1);
    __syncthreads();
    if (!s_last) return;
    __threadfence();

    float sum = 0.0f;
    for (int i = tid; i < NB * NPTS; i += THREADS)
        sum += __int_as_float(g_rmin[i]) + __int_as_float(g_cmin[i]);
    s_red[tid] = sum;
    __syncthreads();
    for (int o = THREADS / 2; o; o >>= 1) {
        if (tid < o) s_red[tid] += s_red[tid + o];
        __syncthreads();
    }
    // values are dist^2/2 -> x2; mean over NB batches and NPTS points.
    if (tid == 0)
        *out = s_red[0] * (2.0f / ((float)NB * (float)NPTS));
}

extern "C" void kernel_launch(void* const* d_in, const int* in_sizes, int n_in,
                              void* d_out, int out_size) {
    const float* pred = (const float*)d_in[0];
    const float* tgt  = (const float*)d_in[1];
    float* out = (float*)d_out;
    (void)in_sizes; (void)n_in; (void)out_size;

    chamfer_init_kernel<<<(NB * NPTS) / 256, 256>>>(pred, tgt);
    chamfer_cross_kernel<<<GRID, THREADS>>>(out);
}

// round 15
// speedup vs baseline: 1.5520x; 1.5520x over previous
#include <cuda_runtime.h>
#include <cstdint>

// Fixed shapes: pred/target = [4, 8192, 3] fp32
#define NB        4
#define NPTS      8192
#define THREADS   128
#define OCC       8
#define IPT       8                    // pred points per lane
#define JT        64                   // targets per tile
#define NCOMBO    (NB * 8)             // 32 (b, ich) combos
#define CPC       32                   // CTAs per combo
#define TPC       4                    // tiles per CTA (32*4 = 128 tiles/combo)
#define GRID      (NCOMBO * CPC)       // 1024 CTAs, perfectly balanced
#define INF_BITS  0x7f800000

// Static device scratch.
__device__ float4       g_ppk[NB * NPTS];   // packed pred: (x,y,z,h)
__device__ float4       g_qpk[NB * NPTS];   // packed tgt:  (x,y,z,h)
__device__ int          g_rmin[NB * NPTS];  // int-ordered fp mins (>=0)
__device__ int          g_cmin[NB * NPTS];
__device__ unsigned int g_done;

// Pack points and reset mins.  32768 threads.
__global__ void chamfer_init_kernel(const float* __restrict__ pred,
                                    const float* __restrict__ tgt) {
    int idx = blockIdx.x * blockDim.x + threadIdx.x;   // 0 .. NB*NPTS-1
    float x = pred[3 * idx], y = pred[3 * idx + 1], z = pred[3 * idx + 2];
    g_ppk[idx] = make_float4(x, y, z, 0.5f * fmaf(x, x, fmaf(y, y, z * z)));
    x = tgt[3 * idx]; y = tgt[3 * idx + 1]; z = tgt[3 * idx + 2];
    g_qpk[idx] = make_float4(x, y, z, 0.5f * fmaf(x, x, fmaf(y, y, z * z)));
    g_rmin[idx] = INF_BITS;
    g_cmin[idx] = INF_BITS;
    if (idx == 0) g_done = 0u;
}

// Symmetric cross kernel, statically scheduled. Each (i,j) computed once:
//   s = h_q - p.q  (3 FFMA, negated-p source modifiers, q.w = +h_q)
//   rows: min(s) (+h_p at flush);  cols: t = h_p + s (FFMA-imm), 8-tree,
//   systolic SHFL ride (1 SHFL per 256 pairs).
// One __syncthreads per tile; next tile register-staged during compute.
__global__ void __launch_bounds__(THREADS, OCC)
chamfer_cross_kernel(float* __restrict__ out) {
    // Double tile buffer, duplicated halves: sq[pc][h][m] = q[h*32 + (m&31)]
    __shared__ float4 sq[2][2][64];
    __shared__ float  scol[2][4][JT];   // double-buffered col mins
    __shared__ int    s_last;
    __shared__ float  s_red[THREADS];

    const int bid   = blockIdx.x;
    const int combo = bid & (NCOMBO - 1);
    const int cidx  = bid >> 5;            // 0..31: index within combo
    const int b     = combo >> 3;
    const int ich   = combo & 7;
    const int tid   = threadIdx.x;
    const int w     = tid >> 5;
    const int lane  = tid & 31;

    const float4* Qp = &g_qpk[b * NPTS];
    int* grow = &g_rmin[b * NPTS];
    int* gcol = &g_cmin[b * NPTS];

    // Static tiles for this CTA: cidx*4 + k, k = 0..3.
    const int tbase = cidx * TPC;

    // Staging map: 128 threads <-> 128 duplicated slots.
    const int sh = tid >> 6;               // half
    const int sm = tid & 63;               // slot within half
    const int sj = (sh << 5) + (sm & 31);  // tile-local j this thread stages

    // Register-resident pred points (fixed for whole kernel).
    const int ib = ich * 1024 + w * 256 + lane * IPT;
    const float4* Pp = &g_ppk[b * NPTS + ib];
    float px[IPT], py[IPT], pz[IPT], hp[IPT], smin[IPT];
#pragma unroll
    for (int k = 0; k < IPT; k++) {
        float4 p = Pp[k];
        px[k] = p.x; py[k] = p.y; pz[k] = p.z; hp[k] = p.w;
        smin[k] = __int_as_float(INF_BITS);
    }

    // Prologue: stage tile 0, prefetch tile 1 into registers.
    float4 qreg = Qp[(tbase + 0) * JT + sj];
    sq[0][sh][sm] = qreg;
    qreg = Qp[(tbase + 1) * JT + sj];
    __syncthreads();

#pragma unroll
    for (int k = 0; k < TPC; k++) {
        const int pc = k & 1;
        // Stage tile k+1 (held in qreg) into the free buffer; prefetch k+2.
        if (k < TPC - 1) sq[pc ^ 1][sh][sm] = qreg;
        if (k < TPC - 2) qreg = Qp[(tbase + k + 2) * JT + sj];

        // 64 systolic steps on buffer pc; cm rides one SHFL per step.
#pragma unroll
        for (int h = 0; h < 2; h++) {
            const float4* qp = &sq[pc][h][lane];
            float cm = __int_as_float(INF_BITS);
#pragma unroll 8
            for (int n = 0; n < 32; n++) {
                float4 q = qp[n];                    // LDS.128, ptr bump only
                float tm;
#pragma unroll
                for (int kk = 0; kk < IPT; kk += 2) {
                    float s0 = fmaf(-pz[kk],     q.z, fmaf(-py[kk],     q.y, fmaf(-px[kk],     q.x, q.w)));
                    float s1 = fmaf(-pz[kk + 1], q.z, fmaf(-py[kk + 1], q.y, fmaf(-px[kk + 1], q.x, q.w)));
                    smin[kk]     = fminf(smin[kk],     s0);
                    smin[kk + 1] = fminf(smin[kk + 1], s1);
                    float t0 = fmaf(s0, 1.0f, hp[kk]);     // t = hp + s (FFMA-imm)
                    float t1 = fmaf(s1, 1.0f, hp[kk + 1]);
                    float tp = fminf(t0, t1);
                    tm = (kk == 0) ? tp : fminf(tm, tp);
                }
                cm = fminf(cm, tm);
                cm = __shfl_sync(0xffffffffu, cm, lane + 1);
            }
            scol[pc][w][h * 32 + lane] = cm;
        }

        // Single barrier per tile: STS(k+1) visible, compute(k) done, scol[pc] full.
        __syncthreads();

        // Col combine for tile k (overlaps next tile's compute; scol double-buffered).
        if (tid < JT) {
            float m = fminf(fminf(scol[pc][0][tid], scol[pc][1][tid]),
                            fminf(scol[pc][2][tid], scol[pc][3][tid]));
            atomicMin(&gcol[(tbase + k) * JT + tid], __float_as_int(m));
        }
    }

    // Row flush once per CTA (add hp back here).
#pragma unroll
    for (int k = 0; k < IPT; k++)
        atomicMin(&grow[ib + k], __float_as_int(hp[k] + smin[k]));

    // Last CTA reduces everything to the scalar output.
    __threadfence();
    if (tid == 0) s_last = (atomicAdd(&g_done, 1u) == GRID - 1);
    __syncthreads();
    if (!s_last) return;
    __threadfence();

    float sum = 0.0f;
    for (int i = tid; i < NB * NPTS; i += THREADS)
        sum += __int_as_float(g_rmin[i]) + __int_as_float(g_cmin[i]);
    s_red[tid] = sum;
    __syncthreads();
    for (int o = THREADS / 2; o; o >>= 1) {
        if (tid < o) s_red[tid] += s_red[tid + o];
        __syncthreads();
    }
    // values are dist^2/2 -> x2; mean over NB batches and NPTS points.
    if (tid == 0)
        *out = s_red[0] * (2.0f / ((float)NB * (float)NPTS));
}

extern "C" void kernel_launch(void* const* d_in, const int* in_sizes, int n_in,
                              void* d_out, int out_size) {
    const float* pred = (const float*)d_in[0];
    const float* tgt  = (const float*)d_in[1];
    float* out = (float*)d_out;
    (void)in_sizes; (void)n_in; (void)out_size;

    chamfer_init_kernel<<<(NB * NPTS) / 256, 256>>>(pred, tgt);
    chamfer_cross_kernel<<<GRID, THREADS>>>(out);
}